// round 11
// baseline (speedup 1.0000x reference)
#include <cuda_runtime.h>
#include <cuda_fp16.h>
#include <math.h>
#include <stdint.h>

// Problem constants
#define Bsz  4
#define Lseq 2048
#define Dm   1024
#define Hn   16
#define HD   64
#define Mrows (Bsz*Lseq)   // 8192
#define QLD  3072          // fused qkv row stride (halves)

// Scratch (device globals — no allocation allowed)
__device__ __half g_xh  [(size_t)Mrows * Dm];
__device__ __half g_wh  [(size_t)3 * Dm * Dm];
__device__ __half g_woh [(size_t)Dm * Dm];
__device__ __half g_qkvh[(size_t)Mrows * QLD];
__device__ __half g_th  [(size_t)Mrows * Dm];
__device__ __half g_vth [(size_t)Bsz * Hn * HD * Lseq];
__device__ __half g_Ah  [(size_t)Bsz * Hn * Lseq * Lseq]; // fp16 copy of A

// ---------------------------------------------------------------------------
__device__ __forceinline__ void cpa16(uint32_t daddr, const void* src) {
    asm volatile("cp.async.ca.shared.global [%0], [%1], 16;" :: "r"(daddr), "l"(src));
}
__device__ __forceinline__ void cpa_commit() { asm volatile("cp.async.commit_group;"); }
__device__ __forceinline__ uint32_t smem_u32(const void* p) {
    return (uint32_t)__cvta_generic_to_shared(p);
}
__device__ __forceinline__ void ldsm4(uint32_t* r, uint32_t a) {
    asm volatile("ldmatrix.sync.aligned.m8n8.x4.shared.b16 {%0,%1,%2,%3}, [%4];"
                 : "=r"(r[0]), "=r"(r[1]), "=r"(r[2]), "=r"(r[3]) : "r"(a));
}
__device__ __forceinline__ void mmaf16(float* d, const uint32_t* a, uint32_t b0, uint32_t b1) {
    asm volatile(
        "mma.sync.aligned.m16n8k16.row.col.f32.f16.f16.f32 "
        "{%0,%1,%2,%3}, {%4,%5,%6,%7}, {%8,%9}, {%0,%1,%2,%3};"
        : "+f"(d[0]), "+f"(d[1]), "+f"(d[2]), "+f"(d[3])
        : "r"(a[0]), "r"(a[1]), "r"(a[2]), "r"(a[3]), "r"(b0), "r"(b1));
}
// pack two fp32 -> one fp16x2 register
__device__ __forceinline__ uint32_t packh2(float lo, float hi) {
    uint32_t u;
    asm("cvt.rn.f16x2.f32 %0, %1, %2;" : "=r"(u) : "f"(hi), "f"(lo));
    return u;
}

// ---------------------------------------------------------------------------
// fp16 NT GEMM: C = alpha * A[M,K] @ B[N,K]^T (+bias)
// MODE 0: proj -> fp16 C.  MODE 2: AV (z-batched A, vT) -> fp16 C per head.
// MODE 3: out proj -> fp32 C + bias.
// ---------------------------------------------------------------------------
template<int BN, int MODE>
__global__ __launch_bounds__(256) void hgemm(
    const __half* __restrict__ Ag, const __half* __restrict__ Bg,
    const float* __restrict__ bias, void* __restrict__ Cg,
    int K, int lda, int ldb, int ldc, float alpha)
{
    constexpr int WN = BN / 4;
    constexpr int NG = WN / 16;
    constexpr int NJ = WN / 8;
    constexpr int ABYTES = 128 * 64;
    constexpr int BBYTES = BN * 64;
    constexpr int STAGE = ABYTES + BBYTES;

    extern __shared__ char smem[];
    const uint32_t sb = smem_u32(smem);

    const int tid = threadIdx.x;
    const int w = tid >> 5, lane = tid & 31;
    const int wm = (w >> 2) * 64, wn = (w & 3) * WN;
    const int g = lane >> 2, tig = lane & 3;
    const int l15 = lane & 15, lh = lane >> 4;
    const int sel = (l15 >> 1) & 3;

    const int m0 = blockIdx.y * 128;
    const int n0 = blockIdx.x * BN;
    const int z  = blockIdx.z;

    const __half* Ab;
    const __half* Bb;
    float* Cf = nullptr;
    __half* Ch = nullptr;

    if (MODE == 2) {
        Ab = Ag + (size_t)z * Lseq * Lseq + (size_t)m0 * lda;
        Bb = Bg + (size_t)z * HD * Lseq + (size_t)n0 * ldb;
        Ch = (__half*)Cg + ((size_t)(z >> 4) * Lseq + m0) * Dm + (size_t)(z & 15) * HD + n0;
    } else {
        Ab = Ag + (size_t)m0 * lda;
        Bb = Bg + (size_t)n0 * ldb;
        if (MODE == 0) Ch = (__half*)Cg + (size_t)m0 * ldc + n0;
        else           Cf = (float*)Cg + (size_t)m0 * ldc + n0;
    }

    float acc[4][NJ][4];
    #pragma unroll
    for (int i = 0; i < 4; i++)
        #pragma unroll
        for (int j = 0; j < NJ; j++)
            #pragma unroll
            for (int r = 0; r < 4; r++) acc[i][j][r] = 0.f;

    const int nk = K / 32;

    auto ldA = [&](int kt, int st) {
        const uint32_t base = sb + st * STAGE;
        const int r = tid >> 1;
        const int c0 = (tid & 1) * 2;
        const __half* src = Ab + (size_t)r * lda + kt * 32;
        #pragma unroll
        for (int c = 0; c < 2; c++) {
            const int cc = c0 + c;
            cpa16(base + r * 64 + ((cc ^ ((r >> 1) & 3)) * 16), src + cc * 8);
        }
    };
    auto ldB = [&](int kt, int st) {
        const uint32_t base = sb + st * STAGE + ABYTES;
        if (BN == 128) {
            const int r = tid >> 1;
            const int c0 = (tid & 1) * 2;
            const __half* src = Bb + (size_t)r * ldb + kt * 32;
            #pragma unroll
            for (int c = 0; c < 2; c++) {
                const int cc = c0 + c;
                cpa16(base + r * 64 + ((cc ^ ((r >> 1) & 3)) * 16), src + cc * 8);
            }
        } else {
            const int r = tid >> 2;
            const int cc = tid & 3;
            const __half* src = Bb + (size_t)r * ldb + kt * 32;
            cpa16(base + r * 64 + ((cc ^ ((r >> 1) & 3)) * 16), src + cc * 8);
        }
    };

    int issued = 0;
    #pragma unroll
    for (int t = 0; t < 3; t++)
        if (t < nk) { ldA(t, t); ldB(t, t); cpa_commit(); issued++; }

    for (int kt = 0; kt < nk; kt++) {
        const int pend = issued - (kt + 1);
        if (pend <= 0)      asm volatile("cp.async.wait_group 0;");
        else if (pend == 1) asm volatile("cp.async.wait_group 1;");
        else                asm volatile("cp.async.wait_group 2;");
        __syncthreads();

        const int st = kt % 3;
        const uint32_t aB = sb + st * STAGE;
        const uint32_t bB = aB + ABYTES;

        #pragma unroll
        for (int ks = 0; ks < 2; ks++) {
            const uint32_t chunk = ((uint32_t)(lh + 2 * ks) ^ (uint32_t)sel) * 16;
            uint32_t af[4][4];
            #pragma unroll
            for (int i = 0; i < 4; i++)
                ldsm4(af[i], aB + (wm + 16 * i + l15) * 64 + chunk);
            uint32_t bf[NG][4];
            #pragma unroll
            for (int jg = 0; jg < NG; jg++)
                ldsm4(bf[jg], bB + (wn + 16 * jg + l15) * 64 + chunk);
            #pragma unroll
            for (int i = 0; i < 4; i++)
                #pragma unroll
                for (int jg = 0; jg < NG; jg++) {
                    mmaf16(acc[i][2 * jg + 0], af[i], bf[jg][0], bf[jg][2]);
                    mmaf16(acc[i][2 * jg + 1], af[i], bf[jg][1], bf[jg][3]);
                }
        }
        __syncthreads();

        if (issued < nk) {
            ldA(issued, issued % 3); ldB(issued, issued % 3);
            cpa_commit();
            issued++;
        }
    }

    #pragma unroll
    for (int i = 0; i < 4; i++) {
        const int row = wm + 16 * i + g;
        #pragma unroll
        for (int j = 0; j < NJ; j++) {
            const int col = wn + 8 * j + 2 * tig;
            float a0 = acc[i][j][0], a1 = acc[i][j][1];
            float a2 = acc[i][j][2], a3 = acc[i][j][3];
            if (MODE == 3) {
                const float b0 = bias[n0 + col], b1 = bias[n0 + col + 1];
                a0 += b0; a1 += b1; a2 += b0; a3 += b1;
            }
            if (MODE == 0 || MODE == 2) {
                *(uint32_t*)(Ch + (size_t)row * ldc + col)       = packh2(a0, a1);
                *(uint32_t*)(Ch + (size_t)(row + 8) * ldc + col) = packh2(a2, a3);
            } else {
                *(float2*)(Cf + (size_t)row * ldc + col)       = make_float2(a0, a1);
                *(float2*)(Cf + (size_t)(row + 8) * ldc + col) = make_float2(a2, a3);
            }
        }
    }
}

// ---------------------------------------------------------------------------
// Fused scores + softmax (round-6 structure), widened to 512 threads.
// One CTA = 16 query rows of one (b,h). Writes fp32 A + fp16 Ah.
// smem: Q 2KB | K dblbuf 2x32KB | stats 128B | scores 16x2056 fp32
// ---------------------------------------------------------------------------
#define ASM_Q 0
#define ASM_K 2048
#define ASM_STAT (2048 + 65536)        // 67584
#define ASM_S (ASM_STAT + 128)         // 67712
#define SSTRIDE 2056
#define ASM_TOTAL (ASM_S + 16 * SSTRIDE * 4)   // 199296

__global__ __launch_bounds__(512) void attn_fused(
    const __half* __restrict__ qkvh, float* __restrict__ Aout, __half* __restrict__ Ah)
{
    extern __shared__ char smem[];
    const uint32_t sb = smem_u32(smem);
    float* scoresS = (float*)(smem + ASM_S);
    float* statS   = (float*)(smem + ASM_STAT);

    const int tid = threadIdx.x;
    const int w = tid >> 5, lane = tid & 31;      // 16 warps
    const int l15 = lane & 15, lh = lane >> 4, sel = (l15 >> 1) & 3;
    const int g = lane >> 2, tig = lane & 3;

    const int l0 = blockIdx.x * 16;
    const int z  = blockIdx.y;
    const int b = z >> 4, h = z & 15;

    const __half* qb = qkvh + ((size_t)b * Lseq + l0) * QLD + h * HD;
    const __half* kb = qkvh + (size_t)b * Lseq * QLD + Dm + h * HD;

    // Q load (with K panel 0's commit group)
    if (tid < 128) {
        const int row = tid >> 3, col8 = tid & 7;
        const int p = col8 >> 2, c = col8 & 3;
        cpa16(sb + ASM_Q + p * 1024 + row * 64 + ((c ^ ((row >> 1) & 3)) * 16),
              qb + (size_t)row * QLD + col8 * 8);
    }
    // K panel: 256 s-rows x 64 d; 512 threads, 4 chunks each
    auto ldK = [&](int nt, int buf) {
        const int row = tid >> 1;                 // 0..255
        const int p = tid & 1;                    // k32-half
        const uint32_t base = sb + ASM_K + buf * 32768 + p * 16384 + row * 64;
        const __half* src = kb + (size_t)(nt * 256 + row) * QLD + p * 32;
        #pragma unroll
        for (int c = 0; c < 4; c++)
            cpa16(base + ((c ^ ((row >> 1) & 3)) * 16), src + c * 8);
    };
    ldK(0, 0); cpa_commit();
    ldK(1, 1); cpa_commit();

    asm volatile("cp.async.wait_group 1;");
    __syncthreads();

    // Q fragments (held through scores phase)
    uint32_t qf[4][4];
    #pragma unroll
    for (int kk = 0; kk < 4; kk++) {
        const int kh = kk >> 1, ks = kk & 1;
        ldsm4(qf[kk], sb + ASM_Q + kh * 1024 + l15 * 64 + (((lh + 2 * ks) ^ sel) * 16));
    }

    // ---- scores phase: warp w owns cols w*16 .. +16 of each 256-panel ----
    for (int nt = 0; nt < 8; nt++) {
        if (nt > 0) {
            if (nt < 7) asm volatile("cp.async.wait_group 1;");
            else        asm volatile("cp.async.wait_group 0;");
            __syncthreads();
        }
        const uint32_t Kb = sb + ASM_K + (nt & 1) * 32768;

        float acc[2][4];
        #pragma unroll
        for (int j = 0; j < 2; j++)
            #pragma unroll
            for (int r = 0; r < 4; r++) acc[j][r] = 0.f;

        #pragma unroll
        for (int kk = 0; kk < 4; kk++) {
            const int kh = kk >> 1, ks = kk & 1;
            const uint32_t chunk = (((uint32_t)lh + 2 * ks) ^ (uint32_t)sel) * 16;
            uint32_t bf[4];
            ldsm4(bf, Kb + kh * 16384 + (w * 16 + l15) * 64 + chunk);
            mmaf16(acc[0], qf[kk], bf[0], bf[2]);
            mmaf16(acc[1], qf[kk], bf[1], bf[3]);
        }

        #pragma unroll
        for (int j = 0; j < 2; j++) {
            const int col = nt * 256 + w * 16 + j * 8 + 2 * tig;
            *(float2*)&scoresS[g * SSTRIDE + col] =
                make_float2(acc[j][0] * 0.125f, acc[j][1] * 0.125f);
            *(float2*)&scoresS[(g + 8) * SSTRIDE + col] =
                make_float2(acc[j][2] * 0.125f, acc[j][3] * 0.125f);
        }
        __syncthreads();
        if (nt + 2 < 8) { ldK(nt + 2, nt & 1); cpa_commit(); }
    }

    // ---- stats: warp w owns row w ----
    {
        const float* rp = &scoresS[w * SSTRIDE];
        float vals[64];
        float m = -INFINITY;
        #pragma unroll
        for (int c = 0; c < 16; c++) {
            float4 vv = *(const float4*)&rp[lane * 4 + c * 128];
            vals[4 * c + 0] = vv.x; vals[4 * c + 1] = vv.y;
            vals[4 * c + 2] = vv.z; vals[4 * c + 3] = vv.w;
            m = fmaxf(m, fmaxf(fmaxf(vv.x, vv.y), fmaxf(vv.z, vv.w)));
        }
        #pragma unroll
        for (int o = 16; o; o >>= 1) m = fmaxf(m, __shfl_xor_sync(0xffffffffu, m, o));
        float s = 0.f;
        #pragma unroll
        for (int i = 0; i < 64; i++) s += __expf(vals[i] - m);
        #pragma unroll
        for (int o = 16; o; o >>= 1) s += __shfl_xor_sync(0xffffffffu, s, o);
        if (lane == 0) { statS[w] = m; statS[16 + w] = 1.0f / s; }
    }
    __syncthreads();

    // ---- convert + write: 32 threads per row, 64 cols per thread ----
    {
        const int crow = tid >> 5;         // 0..15
        const int cg = tid & 31;           // 0..31
        const float rm   = statS[crow];
        const float rinv = statS[16 + crow];
        const float* rp = &scoresS[crow * SSTRIDE + cg * 64];
        float* op = Aout + ((size_t)z * Lseq + l0 + crow) * Lseq + cg * 64;
        __half* hp = Ah + ((size_t)z * Lseq + l0 + crow) * Lseq + cg * 64;
        #pragma unroll
        for (int q = 0; q < 16; q++) {
            float4 v = *(const float4*)(rp + 4 * q);
            v.x = __expf(v.x - rm) * rinv;
            v.y = __expf(v.y - rm) * rinv;
            v.z = __expf(v.z - rm) * rinv;
            v.w = __expf(v.w - rm) * rinv;
            *(float4*)(op + 4 * q) = v;
            uint2 hh;
            hh.x = packh2(v.x, v.y);
            hh.y = packh2(v.z, v.w);
            *(uint2*)(hp + 4 * q) = hh;
        }
    }
}

// ---------------------------------------------------------------------------
__global__ void cvt_h(const float* __restrict__ s, __half* __restrict__ d, int n8)
{
    int i = blockIdx.x * blockDim.x + threadIdx.x;
    if (i < n8) {
        float4 v0 = ((const float4*)s)[2 * i];
        float4 v1 = ((const float4*)s)[2 * i + 1];
        uint4 o;
        o.x = packh2(v0.x, v0.y);
        o.y = packh2(v0.z, v0.w);
        o.z = packh2(v1.x, v1.y);
        o.w = packh2(v1.z, v1.w);
        ((uint4*)d)[i] = o;
    }
}

// ---------------------------------------------------------------------------
__global__ __launch_bounds__(256) void transpose_v(
    const __half* __restrict__ qkvh, __half* __restrict__ vt)
{
    __shared__ __half tile[32][33];
    const int z = blockIdx.z, b = z >> 4, h = z & 15;
    const int s0 = blockIdx.x * 32;
    const int d0 = blockIdx.y * 32;
    const int tx = threadIdx.x, ty = threadIdx.y;

    const __half* src = qkvh + (size_t)b * Lseq * QLD + 2 * Dm + (size_t)h * HD;
    #pragma unroll
    for (int i = 0; i < 32; i += 8)
        tile[ty + i][tx] = src[(size_t)(s0 + ty + i) * QLD + d0 + tx];
    __syncthreads();
    __half* dst = vt + (size_t)z * HD * Lseq;
    #pragma unroll
    for (int i = 0; i < 32; i += 8)
        dst[(size_t)(d0 + ty + i) * Lseq + s0 + tx] = tile[tx][ty + i];
}

// ---------------------------------------------------------------------------
extern "C" void kernel_launch(void* const* d_in, const int* in_sizes, int n_in,
                              void* d_out, int out_size)
{
    const float* x  = (const float*)d_in[0];
    // d_in[1] = key_indices (unused by the reference)
    const float* Wq = (const float*)d_in[2];
    const float* Wk = (const float*)d_in[3];
    const float* Wv = (const float*)d_in[4];
    const float* Wo = (const float*)d_in[5];
    const float* bo = (const float*)d_in[6];

    float* outp = (float*)d_out;
    float* Aout = outp + (size_t)Mrows * Dm;

    __half *xh, *wh, *woh, *qkvh, *th, *vth, *Ah;
    cudaGetSymbolAddress((void**)&xh,   g_xh);
    cudaGetSymbolAddress((void**)&wh,   g_wh);
    cudaGetSymbolAddress((void**)&woh,  g_woh);
    cudaGetSymbolAddress((void**)&qkvh, g_qkvh);
    cudaGetSymbolAddress((void**)&th,   g_th);
    cudaGetSymbolAddress((void**)&vth,  g_vth);
    cudaGetSymbolAddress((void**)&Ah,   g_Ah);

    const int SM128 = 3 * (8192 + 8192);
    const int SM64  = 3 * (8192 + 4096);
    cudaFuncSetAttribute(hgemm<128, 0>, cudaFuncAttributeMaxDynamicSharedMemorySize, SM128);
    cudaFuncSetAttribute(hgemm<128, 3>, cudaFuncAttributeMaxDynamicSharedMemorySize, SM128);
    cudaFuncSetAttribute(hgemm<64, 2>,  cudaFuncAttributeMaxDynamicSharedMemorySize, SM64);
    cudaFuncSetAttribute(attn_fused,    cudaFuncAttributeMaxDynamicSharedMemorySize, ASM_TOTAL);

    // fp16 conversions
    const int nx8 = Mrows * Dm / 8;
    const int nw8 = Dm * Dm / 8;
    cvt_h<<<(nx8 + 255) / 256, 256>>>(x,  xh,               nx8);
    cvt_h<<<(nw8 + 255) / 256, 256>>>(Wq, wh,               nw8);
    cvt_h<<<(nw8 + 255) / 256, 256>>>(Wk, wh + Dm * Dm,     nw8);
    cvt_h<<<(nw8 + 255) / 256, 256>>>(Wv, wh + 2 * Dm * Dm, nw8);
    cvt_h<<<(nw8 + 255) / 256, 256>>>(Wo, woh,              nw8);

    // fused QKV projection
    {
        dim3 g(QLD / 128, Mrows / 128, 1);
        hgemm<128, 0><<<g, 256, SM128>>>(xh, wh, nullptr, qkvh,
                                         Dm, Dm, Dm, QLD, 1.0f);
    }
    // fused scores + softmax -> fp32 A + fp16 Ah
    {
        dim3 g(Lseq / 16, Bsz * Hn);   // (128, 64)
        attn_fused<<<g, 512, ASM_TOTAL>>>(qkvh, Aout, Ah);
    }
    // transpose v -> vT[z][d][s]
    {
        dim3 g(Lseq / 32, HD / 32, Bsz * Hn);
        transpose_v<<<g, dim3(32, 8)>>>(qkvh, vth);
    }
    // AV
    {
        dim3 g(1, Lseq / 128, Bsz * Hn);
        hgemm<64, 2><<<g, 256, SM64>>>(Ah, vth, nullptr, th,
                                       Lseq, Lseq, Lseq, Dm, 1.0f);
    }
    // output projection with bias
    {
        dim3 g(Dm / 128, Mrows / 128, 1);
        hgemm<128, 3><<<g, 256, SM128>>>(th, woh, bo, outp,
                                         Dm, Dm, Dm, Dm, 1.0f);
    }
}

// round 12
// speedup vs baseline: 2.1346x; 2.1346x over previous
#include <cuda_runtime.h>
#include <cuda_fp16.h>
#include <math.h>
#include <stdint.h>

// Problem constants
#define Bsz  4
#define Lseq 2048
#define Dm   1024
#define Hn   16
#define HD   64
#define Mrows (Bsz*Lseq)   // 8192
#define QLD  3072          // fused qkv row stride (halves)

// Scratch (device globals — no allocation allowed)
__device__ __half g_xh  [(size_t)Mrows * Dm];
__device__ __half g_wh  [(size_t)3 * Dm * Dm];
__device__ __half g_woh [(size_t)Dm * Dm];
__device__ __half g_qkvh[(size_t)Mrows * QLD];
__device__ __half g_th  [(size_t)Mrows * Dm];
__device__ __half g_vth [(size_t)Bsz * Hn * HD * Lseq];
__device__ __half g_Ah  [(size_t)Bsz * Hn * Lseq * Lseq]; // fp16 copy of A

// ---------------------------------------------------------------------------
__device__ __forceinline__ void cpa16(uint32_t daddr, const void* src) {
    asm volatile("cp.async.ca.shared.global [%0], [%1], 16;" :: "r"(daddr), "l"(src));
}
__device__ __forceinline__ void cpa_commit() { asm volatile("cp.async.commit_group;"); }
__device__ __forceinline__ uint32_t smem_u32(const void* p) {
    return (uint32_t)__cvta_generic_to_shared(p);
}
__device__ __forceinline__ void ldsm4(uint32_t* r, uint32_t a) {
    asm volatile("ldmatrix.sync.aligned.m8n8.x4.shared.b16 {%0,%1,%2,%3}, [%4];"
                 : "=r"(r[0]), "=r"(r[1]), "=r"(r[2]), "=r"(r[3]) : "r"(a));
}
__device__ __forceinline__ void mmaf16(float* d, const uint32_t* a, uint32_t b0, uint32_t b1) {
    asm volatile(
        "mma.sync.aligned.m16n8k16.row.col.f32.f16.f16.f32 "
        "{%0,%1,%2,%3}, {%4,%5,%6,%7}, {%8,%9}, {%0,%1,%2,%3};"
        : "+f"(d[0]), "+f"(d[1]), "+f"(d[2]), "+f"(d[3])
        : "r"(a[0]), "r"(a[1]), "r"(a[2]), "r"(a[3]), "r"(b0), "r"(b1));
}
// pack two fp32 -> one fp16x2 register
__device__ __forceinline__ uint32_t packh2(float lo, float hi) {
    uint32_t u;
    asm("cvt.rn.f16x2.f32 %0, %1, %2;" : "=r"(u) : "f"(hi), "f"(lo));
    return u;
}

// ---------------------------------------------------------------------------
// fp16 NT GEMM: C = alpha * A[M,K] @ B[N,K]^T (+bias)
// 4-stage cp.async pipeline, ONE barrier per K-iter.
// MODE 0: proj -> fp16 C.  MODE 2: AV (z-batched A, vT) -> fp16 C per head.
// MODE 3: out proj -> fp32 C + bias.
// ---------------------------------------------------------------------------
template<int BN, int MODE>
__global__ __launch_bounds__(256) void hgemm(
    const __half* __restrict__ Ag, const __half* __restrict__ Bg,
    const float* __restrict__ bias, void* __restrict__ Cg,
    int K, int lda, int ldb, int ldc, float alpha)
{
    constexpr int WN = BN / 4;
    constexpr int NG = WN / 16;
    constexpr int NJ = WN / 8;
    constexpr int ABYTES = 128 * 64;
    constexpr int BBYTES = BN * 64;
    constexpr int STAGE = ABYTES + BBYTES;

    extern __shared__ char smem[];
    const uint32_t sb = smem_u32(smem);

    const int tid = threadIdx.x;
    const int w = tid >> 5, lane = tid & 31;
    const int wm = (w >> 2) * 64, wn = (w & 3) * WN;
    const int g = lane >> 2, tig = lane & 3;
    const int l15 = lane & 15, lh = lane >> 4;
    const int sel = (l15 >> 1) & 3;

    const int m0 = blockIdx.y * 128;
    const int n0 = blockIdx.x * BN;
    const int z  = blockIdx.z;

    const __half* Ab;
    const __half* Bb;
    float* Cf = nullptr;
    __half* Ch = nullptr;

    if (MODE == 2) {
        Ab = Ag + (size_t)z * Lseq * Lseq + (size_t)m0 * lda;
        Bb = Bg + (size_t)z * HD * Lseq + (size_t)n0 * ldb;
        Ch = (__half*)Cg + ((size_t)(z >> 4) * Lseq + m0) * Dm + (size_t)(z & 15) * HD + n0;
    } else {
        Ab = Ag + (size_t)m0 * lda;
        Bb = Bg + (size_t)n0 * ldb;
        if (MODE == 0) Ch = (__half*)Cg + (size_t)m0 * ldc + n0;
        else           Cf = (float*)Cg + (size_t)m0 * ldc + n0;
    }

    float acc[4][NJ][4];
    #pragma unroll
    for (int i = 0; i < 4; i++)
        #pragma unroll
        for (int j = 0; j < NJ; j++)
            #pragma unroll
            for (int r = 0; r < 4; r++) acc[i][j][r] = 0.f;

    const int nk = K / 32;

    auto ldA = [&](int kt, int st) {
        const uint32_t base = sb + st * STAGE;
        const int r = tid >> 1;
        const int c0 = (tid & 1) * 2;
        const __half* src = Ab + (size_t)r * lda + kt * 32;
        #pragma unroll
        for (int c = 0; c < 2; c++) {
            const int cc = c0 + c;
            cpa16(base + r * 64 + ((cc ^ ((r >> 1) & 3)) * 16), src + cc * 8);
        }
    };
    auto ldB = [&](int kt, int st) {
        const uint32_t base = sb + st * STAGE + ABYTES;
        if (BN == 128) {
            const int r = tid >> 1;
            const int c0 = (tid & 1) * 2;
            const __half* src = Bb + (size_t)r * ldb + kt * 32;
            #pragma unroll
            for (int c = 0; c < 2; c++) {
                const int cc = c0 + c;
                cpa16(base + r * 64 + ((cc ^ ((r >> 1) & 3)) * 16), src + cc * 8);
            }
        } else {
            const int r = tid >> 2;
            const int cc = tid & 3;
            const __half* src = Bb + (size_t)r * ldb + kt * 32;
            cpa16(base + r * 64 + ((cc ^ ((r >> 1) & 3)) * 16), src + cc * 8);
        }
    };

    int issued = 0;
    #pragma unroll
    for (int t = 0; t < 3; t++)
        if (t < nk) { ldA(t, t); ldB(t, t); cpa_commit(); issued++; }

    for (int kt = 0; kt < nk; kt++) {
        const int pend = issued - (kt + 1);
        if (pend <= 0)      asm volatile("cp.async.wait_group 0;");
        else if (pend == 1) asm volatile("cp.async.wait_group 1;");
        else                asm volatile("cp.async.wait_group 2;");
        __syncthreads();
        // prefetch into stage (kt+3)&3 == (kt-1)&3: all warps finished reading
        // stage kt-1 before the barrier above -> safe with a single barrier.
        const int st = kt & 3;
        const uint32_t aB = sb + st * STAGE;
        const uint32_t bB = aB + ABYTES;

        #pragma unroll
        for (int ks = 0; ks < 2; ks++) {
            const uint32_t chunk = ((uint32_t)(lh + 2 * ks) ^ (uint32_t)sel) * 16;
            uint32_t af[4][4];
            #pragma unroll
            for (int i = 0; i < 4; i++)
                ldsm4(af[i], aB + (wm + 16 * i + l15) * 64 + chunk);
            uint32_t bf[NG][4];
            #pragma unroll
            for (int jg = 0; jg < NG; jg++)
                ldsm4(bf[jg], bB + (wn + 16 * jg + l15) * 64 + chunk);
            #pragma unroll
            for (int i = 0; i < 4; i++)
                #pragma unroll
                for (int jg = 0; jg < NG; jg++) {
                    mmaf16(acc[i][2 * jg + 0], af[i], bf[jg][0], bf[jg][2]);
                    mmaf16(acc[i][2 * jg + 1], af[i], bf[jg][1], bf[jg][3]);
                }
        }

        if (issued < nk) {
            ldA(issued, issued & 3); ldB(issued, issued & 3);
            cpa_commit();
            issued++;
        }
    }

    #pragma unroll
    for (int i = 0; i < 4; i++) {
        const int row = wm + 16 * i + g;
        #pragma unroll
        for (int j = 0; j < NJ; j++) {
            const int col = wn + 8 * j + 2 * tig;
            float a0 = acc[i][j][0], a1 = acc[i][j][1];
            float a2 = acc[i][j][2], a3 = acc[i][j][3];
            if (MODE == 3) {
                const float b0 = bias[n0 + col], b1 = bias[n0 + col + 1];
                a0 += b0; a1 += b1; a2 += b0; a3 += b1;
            }
            if (MODE == 0 || MODE == 2) {
                *(uint32_t*)(Ch + (size_t)row * ldc + col)       = packh2(a0, a1);
                *(uint32_t*)(Ch + (size_t)(row + 8) * ldc + col) = packh2(a2, a3);
            } else {
                *(float2*)(Cf + (size_t)row * ldc + col)       = make_float2(a0, a1);
                *(float2*)(Cf + (size_t)(row + 8) * ldc + col) = make_float2(a2, a3);
            }
        }
    }
}

// ---------------------------------------------------------------------------
// Fused scores + softmax (round-6 structure, 256 threads).
// One CTA = 16 query rows of one (b,h). Writes fp32 A + fp16 Ah.
// smem: Q 2KB | K dblbuf 2x32KB | scores 16x2056 fp32 (128.5KB)
// ---------------------------------------------------------------------------
#define ASM_Q 0
#define ASM_K 2048
#define ASM_S (2048 + 65536)
#define SSTRIDE 2056
#define ASM_TOTAL (ASM_S + 16 * SSTRIDE * 4)

__global__ __launch_bounds__(256) void attn_fused(
    const __half* __restrict__ qkvh, float* __restrict__ Aout, __half* __restrict__ Ah)
{
    extern __shared__ char smem[];
    const uint32_t sb = smem_u32(smem);
    float* scoresS = (float*)(smem + ASM_S);

    const int tid = threadIdx.x;
    const int w = tid >> 5, lane = tid & 31;
    const int l15 = lane & 15, lh = lane >> 4, sel = (l15 >> 1) & 3;
    const int g = lane >> 2, tig = lane & 3;

    const int l0 = blockIdx.x * 16;
    const int z  = blockIdx.y;
    const int b = z >> 4, h = z & 15;

    const __half* qb = qkvh + ((size_t)b * Lseq + l0) * QLD + h * HD;
    const __half* kb = qkvh + (size_t)b * Lseq * QLD + Dm + h * HD;

    // Q load (group 0, with K panel 0)
    if (tid < 128) {
        const int row = tid >> 3, col8 = tid & 7;
        const int p = col8 >> 2, c = col8 & 3;
        cpa16(sb + ASM_Q + p * 1024 + row * 64 + ((c ^ ((row >> 1) & 3)) * 16),
              qb + (size_t)row * QLD + col8 * 8);
    }
    auto ldK = [&](int nt, int buf) {
        const int col8 = tid & 7;
        const int p = col8 >> 2, c = col8 & 3;
        #pragma unroll
        for (int i = 0; i < 8; i++) {
            const int row = (tid >> 3) + i * 32;
            cpa16(sb + ASM_K + buf * 32768 + p * 16384 + row * 64 +
                      ((c ^ ((row >> 1) & 3)) * 16),
                  kb + (size_t)(nt * 256 + row) * QLD + col8 * 8);
        }
    };
    ldK(0, 0); cpa_commit();
    ldK(1, 1); cpa_commit();

    asm volatile("cp.async.wait_group 1;");
    __syncthreads();

    // Q fragments (held for whole kernel)
    uint32_t qf[4][4];
    #pragma unroll
    for (int kk = 0; kk < 4; kk++) {
        const int kh = kk >> 1, ks = kk & 1;
        ldsm4(qf[kk], sb + ASM_Q + kh * 1024 + l15 * 64 + (((lh + 2 * ks) ^ sel) * 16));
    }

    for (int nt = 0; nt < 8; nt++) {
        if (nt > 0) {
            if (nt < 7) asm volatile("cp.async.wait_group 1;");
            else        asm volatile("cp.async.wait_group 0;");
            __syncthreads();
        }
        const uint32_t Kb = sb + ASM_K + (nt & 1) * 32768;

        float acc[4][4];
        #pragma unroll
        for (int j = 0; j < 4; j++)
            #pragma unroll
            for (int r = 0; r < 4; r++) acc[j][r] = 0.f;

        #pragma unroll
        for (int kk = 0; kk < 4; kk++) {
            const int kh = kk >> 1, ks = kk & 1;
            const uint32_t chunk = (((uint32_t)lh + 2 * ks) ^ (uint32_t)sel) * 16;
            uint32_t bf0[4], bf1[4];
            ldsm4(bf0, Kb + kh * 16384 + (w * 32 + l15) * 64 + chunk);
            ldsm4(bf1, Kb + kh * 16384 + (w * 32 + 16 + l15) * 64 + chunk);
            mmaf16(acc[0], qf[kk], bf0[0], bf0[2]);
            mmaf16(acc[1], qf[kk], bf0[1], bf0[3]);
            mmaf16(acc[2], qf[kk], bf1[0], bf1[2]);
            mmaf16(acc[3], qf[kk], bf1[1], bf1[3]);
        }

        #pragma unroll
        for (int j = 0; j < 4; j++) {
            const int col = nt * 256 + w * 32 + j * 8 + 2 * tig;
            *(float2*)&scoresS[g * SSTRIDE + col] =
                make_float2(acc[j][0] * 0.125f, acc[j][1] * 0.125f);
            *(float2*)&scoresS[(g + 8) * SSTRIDE + col] =
                make_float2(acc[j][2] * 0.125f, acc[j][3] * 0.125f);
        }
        __syncthreads();
        if (nt + 2 < 8) { ldK(nt + 2, nt & 1); cpa_commit(); }
    }

    // softmax: warp w handles rows w and w+8 (vals in registers, coalesced I/O)
    #pragma unroll
    for (int rr = 0; rr < 2; rr++) {
        const int r = w + rr * 8;
        const float* rp = &scoresS[r * SSTRIDE];
        float vals[64];
        float m = -INFINITY;
        #pragma unroll
        for (int c = 0; c < 16; c++) {
            float4 vv = *(const float4*)&rp[lane * 4 + c * 128];
            vals[4 * c + 0] = vv.x; vals[4 * c + 1] = vv.y;
            vals[4 * c + 2] = vv.z; vals[4 * c + 3] = vv.w;
            m = fmaxf(m, fmaxf(fmaxf(vv.x, vv.y), fmaxf(vv.z, vv.w)));
        }
        #pragma unroll
        for (int o = 16; o; o >>= 1) m = fmaxf(m, __shfl_xor_sync(0xffffffffu, m, o));

        float s = 0.f;
        #pragma unroll
        for (int i = 0; i < 64; i++) { vals[i] = __expf(vals[i] - m); s += vals[i]; }
        #pragma unroll
        for (int o = 16; o; o >>= 1) s += __shfl_xor_sync(0xffffffffu, s, o);
        const float inv = 1.0f / s;

        float* op = Aout + ((size_t)z * Lseq + l0 + r) * Lseq;
        __half* hp = Ah + ((size_t)z * Lseq + l0 + r) * Lseq;
        #pragma unroll
        for (int c = 0; c < 16; c++) {
            float4 o;
            o.x = vals[4 * c + 0] * inv; o.y = vals[4 * c + 1] * inv;
            o.z = vals[4 * c + 2] * inv; o.w = vals[4 * c + 3] * inv;
            *(float4*)&op[lane * 4 + c * 128] = o;
            uint2 hh;
            hh.x = packh2(o.x, o.y);
            hh.y = packh2(o.z, o.w);
            *(uint2*)&hp[lane * 4 + c * 128] = hh;
        }
    }
}

// ---------------------------------------------------------------------------
__global__ void cvt_h(const float* __restrict__ s, __half* __restrict__ d, int n8)
{
    int i = blockIdx.x * blockDim.x + threadIdx.x;
    if (i < n8) {
        float4 v0 = ((const float4*)s)[2 * i];
        float4 v1 = ((const float4*)s)[2 * i + 1];
        uint4 o;
        o.x = packh2(v0.x, v0.y);
        o.y = packh2(v0.z, v0.w);
        o.z = packh2(v1.x, v1.y);
        o.w = packh2(v1.z, v1.w);
        ((uint4*)d)[i] = o;
    }
}

// merged weight conversion: blockIdx.y selects which tensor
__global__ void cvt_h4(const float* __restrict__ s0, const float* __restrict__ s1,
                       const float* __restrict__ s2, const float* __restrict__ s3,
                       __half* __restrict__ d0, __half* __restrict__ d1,
                       __half* __restrict__ d2, __half* __restrict__ d3, int n8)
{
    int i = blockIdx.x * blockDim.x + threadIdx.x;
    if (i >= n8) return;
    const float* s = (blockIdx.y == 0) ? s0 : (blockIdx.y == 1) ? s1
                   : (blockIdx.y == 2) ? s2 : s3;
    __half* d = (blockIdx.y == 0) ? d0 : (blockIdx.y == 1) ? d1
              : (blockIdx.y == 2) ? d2 : d3;
    float4 v0 = ((const float4*)s)[2 * i];
    float4 v1 = ((const float4*)s)[2 * i + 1];
    uint4 o;
    o.x = packh2(v0.x, v0.y);
    o.y = packh2(v0.z, v0.w);
    o.z = packh2(v1.x, v1.y);
    o.w = packh2(v1.z, v1.w);
    ((uint4*)d)[i] = o;
}

// ---------------------------------------------------------------------------
__global__ __launch_bounds__(256) void transpose_v(
    const __half* __restrict__ qkvh, __half* __restrict__ vt)
{
    __shared__ __half tile[32][33];
    const int z = blockIdx.z, b = z >> 4, h = z & 15;
    const int s0 = blockIdx.x * 32;
    const int d0 = blockIdx.y * 32;
    const int tx = threadIdx.x, ty = threadIdx.y;

    const __half* src = qkvh + (size_t)b * Lseq * QLD + 2 * Dm + (size_t)h * HD;
    #pragma unroll
    for (int i = 0; i < 32; i += 8)
        tile[ty + i][tx] = src[(size_t)(s0 + ty + i) * QLD + d0 + tx];
    __syncthreads();
    __half* dst = vt + (size_t)z * HD * Lseq;
    #pragma unroll
    for (int i = 0; i < 32; i += 8)
        dst[(size_t)(d0 + ty + i) * Lseq + s0 + tx] = tile[tx][ty + i];
}

// ---------------------------------------------------------------------------
extern "C" void kernel_launch(void* const* d_in, const int* in_sizes, int n_in,
                              void* d_out, int out_size)
{
    const float* x  = (const float*)d_in[0];
    // d_in[1] = key_indices (unused by the reference)
    const float* Wq = (const float*)d_in[2];
    const float* Wk = (const float*)d_in[3];
    const float* Wv = (const float*)d_in[4];
    const float* Wo = (const float*)d_in[5];
    const float* bo = (const float*)d_in[6];

    float* outp = (float*)d_out;
    float* Aout = outp + (size_t)Mrows * Dm;

    __half *xh, *wh, *woh, *qkvh, *th, *vth, *Ah;
    cudaGetSymbolAddress((void**)&xh,   g_xh);
    cudaGetSymbolAddress((void**)&wh,   g_wh);
    cudaGetSymbolAddress((void**)&woh,  g_woh);
    cudaGetSymbolAddress((void**)&qkvh, g_qkvh);
    cudaGetSymbolAddress((void**)&th,   g_th);
    cudaGetSymbolAddress((void**)&vth,  g_vth);
    cudaGetSymbolAddress((void**)&Ah,   g_Ah);

    const int SM128 = 4 * (8192 + 8192);   // 65536 (4-stage)
    const int SM64  = 4 * (8192 + 4096);   // 49152
    cudaFuncSetAttribute(hgemm<128, 0>, cudaFuncAttributeMaxDynamicSharedMemorySize, SM128);
    cudaFuncSetAttribute(hgemm<128, 3>, cudaFuncAttributeMaxDynamicSharedMemorySize, SM128);
    cudaFuncSetAttribute(hgemm<64, 2>,  cudaFuncAttributeMaxDynamicSharedMemorySize, SM64);
    cudaFuncSetAttribute(attn_fused,    cudaFuncAttributeMaxDynamicSharedMemorySize, ASM_TOTAL);

    // fp16 conversions (x + merged weights)
    const int nx8 = Mrows * Dm / 8;
    const int nw8 = Dm * Dm / 8;
    cvt_h<<<(nx8 + 255) / 256, 256>>>(x, xh, nx8);
    {
        dim3 g((nw8 + 255) / 256, 4);
        cvt_h4<<<g, 256>>>(Wq, Wk, Wv, Wo,
                           wh, wh + Dm * Dm, wh + 2 * Dm * Dm, woh, nw8);
    }

    // fused QKV projection
    {
        dim3 g(QLD / 128, Mrows / 128, 1);
        hgemm<128, 0><<<g, 256, SM128>>>(xh, wh, nullptr, qkvh,
                                         Dm, Dm, Dm, QLD, 1.0f);
    }
    // fused scores + softmax -> fp32 A + fp16 Ah
    {
        dim3 g(Lseq / 16, Bsz * Hn);   // (128, 64)
        attn_fused<<<g, 256, ASM_TOTAL>>>(qkvh, Aout, Ah);
    }
    // transpose v -> vT[z][d][s]
    {
        dim3 g(Lseq / 32, HD / 32, Bsz * Hn);
        transpose_v<<<g, dim3(32, 8)>>>(qkvh, vth);
    }
    // AV
    {
        dim3 g(1, Lseq / 128, Bsz * Hn);
        hgemm<64, 2><<<g, 256, SM64>>>(Ah, vth, nullptr, th,
                                       Lseq, Lseq, Lseq, Dm, 1.0f);
    }
    // output projection with bias
    {
        dim3 g(Dm / 128, Mrows / 128, 1);
        hgemm<128, 3><<<g, 256, SM128>>>(th, woh, bo, outp,
                                         Dm, Dm, Dm, Dm, 1.0f);
    }
}